// round 9
// baseline (speedup 1.0000x reference)
#include <cuda_runtime.h>
#include <math.h>

#define N_NODES 50000
#define N_EDGES 800000
#define PER 8
#define CAP 64   // max in-degree slots; deg ~ Poisson(16), P(>=64) ~ 0

// ---- device scratch (static allocations only; zero-initialized at load) ----
__device__ int   g_cnt[N_NODES];                        // in-degree counter (self-resetting)
__device__ __align__(16) int g_esrc[N_NODES * CAP];     // binned src indices per dst
__device__ float g_dinvf[N_NODES];                      // (deg+1)^{-1/2}
__device__ float g_Mz[128];                             // Wz @ LzW[:32]  -> [4][32]
__device__ float g_Mh[128];                             // Wh @ LhW[:32]  -> [4][32]
__device__ float g_cz[32];
__device__ float g_ch[32];
__device__ float g_probs[PER];

// ------------------------------------------------------------------
// Bin edges by destination: one edge per thread (best-measured variant).
// Block 0 lanes 0-31 also fold the gate weights.
__global__ void k_fill(const int* __restrict__ src, const int* __restrict__ dst,
                       const float* __restrict__ Wz, const float* __restrict__ bz,
                       const float* __restrict__ Wh, const float* __restrict__ bh,
                       const float* __restrict__ LzW, const float* __restrict__ Lzb,
                       const float* __restrict__ LhW, const float* __restrict__ Lhb,
                       const float* __restrict__ att) {
    if (blockIdx.x == 0 && threadIdx.x < 32) {
        int j = threadIdx.x;
        float cz = Lzb[j], ch = Lhb[j];
        #pragma unroll 8
        for (int k = 0; k < 32; k++) {
            cz += bz[k] * LzW[k * 32 + j];
            ch += bh[k] * LhW[k * 32 + j];
        }
        g_cz[j] = cz; g_ch[j] = ch;
        #pragma unroll
        for (int f = 0; f < 4; f++) {
            float mz = 0.f, mh = 0.f;
            #pragma unroll 8
            for (int k = 0; k < 32; k++) {
                mz += Wz[f * 32 + k] * LzW[k * 32 + j];
                mh += Wh[f * 32 + k] * LhW[k * 32 + j];
            }
            g_Mz[f * 32 + j] = mz;
            g_Mh[f * 32 + j] = mh;
        }
        if (j == 0) {
            float m = att[0];
            for (int p = 1; p < PER; p++) m = fmaxf(m, att[p]);
            float s = 0.f, e[PER];
            for (int p = 0; p < PER; p++) { e[p] = expf(att[p] - m); s += e[p]; }
            for (int p = 0; p < PER; p++) g_probs[p] = e[p] / s;
        }
    }

    int e = blockIdx.x * blockDim.x + threadIdx.x;
    if (e >= N_EDGES) return;
    int s = __ldg(&src[e]);
    int d = __ldg(&dst[e]);
    int pos = atomicAdd(&g_cnt[d], 1);
    if (pos < CAP) g_esrc[d * CAP + pos] = s;
}

// ------------------------------------------------------------------
// Tiny: dinv table only (200 KB, stays L2/L1-hot for k_fused).
__global__ void k_dinv() {
    int n = blockIdx.x * blockDim.x + threadIdx.x;
    if (n < N_NODES) g_dinvf[n] = rsqrtf((float)g_cnt[n] + 1.0f);
}

// ------------------------------------------------------------------
// Fused gather + GRU + attention + output.  8 lanes per node.
// Gathers RAW x, weighting each edge by dinv[s] (broadcast load within group).
__global__ void k_fused(const float* __restrict__ x,
                        const float* __restrict__ outW, const float* __restrict__ outb,
                        float* __restrict__ out) {
    __shared__ float sMz[128], sMh[128], scz[32], sch[32], sp[PER], sOW[256], sOb[PER];
    int t = threadIdx.x;   // block 256
    if (t < 128) { sMz[t] = g_Mz[t]; sMh[t] = g_Mh[t]; }
    if (t < 32)  { scz[t] = g_cz[t]; sch[t] = g_ch[t]; }
    if (t < PER) { sp[t] = g_probs[t]; sOb[t] = outb[t]; }
    sOW[t] = outW[t];
    __syncthreads();

    int gi = blockIdx.x * blockDim.x + t;
    int n_raw = gi >> 3;
    bool live = (n_raw < N_NODES);
    int n = live ? n_raw : (N_NODES - 1);        // clamp: keep warp uniform for shfl
    int w = t & 31;                              // lane in warp
    int q = w & 7;                               // lane in 8-group
    int gbase = w & ~7;                          // group base lane

    // ---- gather: lane q owns float4 chunk q of the 32-float row ----
    int cnt = g_cnt[n];
    int deg = cnt > CAP ? CAP : cnt;
    const int* row = &g_esrc[n * CAP];
    const float4* x4 = reinterpret_cast<const float4*>(x);

    float4 acc = make_float4(0.f, 0.f, 0.f, 0.f);
    int e = 0;
    for (; e + 4 <= deg; e += 4) {
        int4 s4 = *reinterpret_cast<const int4*>(row + e);   // 16B-aligned (CAP=64)
        float w0 = __ldg(&g_dinvf[s4.x]);
        float w1 = __ldg(&g_dinvf[s4.y]);
        float w2 = __ldg(&g_dinvf[s4.z]);
        float w3 = __ldg(&g_dinvf[s4.w]);
        float4 v0 = x4[s4.x * 8 + q];
        float4 v1 = x4[s4.y * 8 + q];
        float4 v2 = x4[s4.z * 8 + q];
        float4 v3 = x4[s4.w * 8 + q];
        acc.x += w0 * v0.x + w1 * v1.x + w2 * v2.x + w3 * v3.x;
        acc.y += w0 * v0.y + w1 * v1.y + w2 * v2.y + w3 * v3.y;
        acc.z += w0 * v0.z + w1 * v1.z + w2 * v2.z + w3 * v3.z;
        acc.w += w0 * v0.w + w1 * v1.w + w2 * v2.w + w3 * v3.w;
    }
    for (; e < deg; e++) {
        int s = row[e];
        float ws = __ldg(&g_dinvf[s]);
        float4 v = x4[s * 8 + q];
        acc.x += ws * v.x; acc.y += ws * v.y; acc.z += ws * v.z; acc.w += ws * v.w;
    }
    // reset counter for the next graph replay: safe because k_fused reads only
    // its OWN g_cnt[n] (cross-node data comes from the immutable dinv table / x)
    if (live && q == 0) g_cnt[n] = 0;

    float dn = g_dinvf[n];
    float4 xn = x4[n * 8 + q];
    acc.x = dn * (acc.x + dn * xn.x);
    acc.y = dn * (acc.y + dn * xn.y);
    acc.z = dn * (acc.z + dn * xn.z);
    acc.w = dn * (acc.w + dn * xn.w);
    // acc = yf[4q .. 4q+3] of row layout [f=0..3][p=0..7]

    // ---- preload this lane's 4 hidden-channel weight columns ----
    int j0 = q * 4;
    float rMz[4][4], rMh[4][4], rcz[4], rch[4];
    #pragma unroll
    for (int i = 0; i < 4; i++) {
        rcz[i] = scz[j0 + i];
        rch[i] = sch[j0 + i];
        #pragma unroll
        for (int f = 0; f < 4; f++) {
            rMz[f][i] = sMz[f * 32 + j0 + i];
            rMh[f][i] = sMh[f * 32 + j0 + i];
        }
    }

    float Hacc[4] = {0.f, 0.f, 0.f, 0.f};
    #pragma unroll
    for (int p = 0; p < PER; p++) {
        float csel = (p & 3) == 0 ? acc.x : (p & 3) == 1 ? acc.y : (p & 3) == 2 ? acc.z : acc.w;
        int off = p >> 2;
        float y0 = __shfl_sync(0xffffffffu, csel, gbase + 0 + off);
        float y1 = __shfl_sync(0xffffffffu, csel, gbase + 2 + off);
        float y2 = __shfl_sync(0xffffffffu, csel, gbase + 4 + off);
        float y3 = __shfl_sync(0xffffffffu, csel, gbase + 6 + off);
        float pw = sp[p];
        #pragma unroll
        for (int i = 0; i < 4; i++) {
            float az = rcz[i] + y0 * rMz[0][i] + y1 * rMz[1][i] + y2 * rMz[2][i] + y3 * rMz[3][i];
            float ah = rch[i] + y0 * rMh[0][i] + y1 * rMh[1][i] + y2 * rMh[2][i] + y3 * rMh[3][i];
            // sigmoid(-az)*tanh(ah) = (e^{2ah}-1) / ((1+e^{az})(e^{2ah}+1))
            float ea = __expf(az);
            float e2 = __expf(2.0f * fminf(ah, 15.0f));
            float val = __fdividef(e2 - 1.0f, (1.0f + ea) * (e2 + 1.0f));
            Hacc[i] += pw * val;
        }
    }

    // ---- output: partial o[8] over this lane's 4 channels, then 8-lane butterfly ----
    float o[PER];
    #pragma unroll
    for (int k = 0; k < PER; k++) o[k] = sOb[k] * 0.125f;   // split bias so 8-lane sum = bias
    #pragma unroll
    for (int i = 0; i < 4; i++) {
        float r = fmaxf(Hacc[i], 0.0f);
        #pragma unroll
        for (int k = 0; k < PER; k++) o[k] += r * sOW[(j0 + i) * 8 + k];
    }
    #pragma unroll
    for (int m = 1; m <= 4; m <<= 1) {
        #pragma unroll
        for (int k = 0; k < PER; k++)
            o[k] += __shfl_xor_sync(0xffffffffu, o[k], m);
    }
    float val = (q & 4) ? ((q & 2) ? ((q & 1) ? o[7] : o[6]) : ((q & 1) ? o[5] : o[4]))
                        : ((q & 2) ? ((q & 1) ? o[3] : o[2]) : ((q & 1) ? o[1] : o[0]));
    if (live) out[n * 8 + q] = val;
}

// ------------------------------------------------------------------
extern "C" void kernel_launch(void* const* d_in, const int* in_sizes, int n_in,
                              void* d_out, int out_size) {
    const float* x   = (const float*)d_in[0];
    const int* ei    = (const int*)d_in[1];
    const float* Wz  = (const float*)d_in[2];
    const float* bz  = (const float*)d_in[3];
    const float* Wh  = (const float*)d_in[6];
    const float* bh  = (const float*)d_in[7];
    const float* LzW = (const float*)d_in[8];
    const float* Lzb = (const float*)d_in[9];
    const float* LhW = (const float*)d_in[12];
    const float* Lhb = (const float*)d_in[13];
    const float* att = (const float*)d_in[14];
    const float* outW = (const float*)d_in[15];
    const float* outb = (const float*)d_in[16];
    float* out = (float*)d_out;

    const int* src = ei;             // edge_index[0,:]
    const int* dst = ei + N_EDGES;   // edge_index[1,:]

    k_fill<<<(N_EDGES + 255) / 256, 256>>>(src, dst, Wz, bz, Wh, bh,
                                           LzW, Lzb, LhW, Lhb, att);
    k_dinv<<<(N_NODES + 255) / 256, 256>>>();
    k_fused<<<(N_NODES * 8 + 255) / 256, 256>>>(x, outW, outb, out);
}

// round 10
// speedup vs baseline: 1.1779x; 1.1779x over previous
#include <cuda_runtime.h>
#include <math.h>

#define N_NODES 50000
#define N_EDGES 800000
#define PER 8
#define CAP 64   // max in-degree slots; deg ~ Poisson(16), P(>=64) ~ 0

// ---- device scratch (static allocations only; zero-initialized at load) ----
__device__ int   g_cnt[N_NODES];                        // in-degree counter (self-resetting)
__device__ __align__(16) int g_esrc[N_NODES * CAP];     // binned src indices per dst
__device__ __align__(16) float g_Xs[N_NODES * 32];      // dinv[n] * x[n]  [N,4,8]
__device__ float g_Mz[128];                             // Wz @ LzW[:32]  -> [4][32]
__device__ float g_Mh[128];                             // Wh @ LhW[:32]  -> [4][32]
__device__ float g_cz[32];
__device__ float g_ch[32];
__device__ float g_probs[PER];

// ------------------------------------------------------------------
// Bin edges by destination (4 edges/thread, int4). Block 0 lanes 0-31 also
// fold the gate weights.
__global__ void k_fill(const int4* __restrict__ src4, const int4* __restrict__ dst4,
                       const float* __restrict__ Wz, const float* __restrict__ bz,
                       const float* __restrict__ Wh, const float* __restrict__ bh,
                       const float* __restrict__ LzW, const float* __restrict__ Lzb,
                       const float* __restrict__ LhW, const float* __restrict__ Lhb,
                       const float* __restrict__ att) {
    if (blockIdx.x == 0 && threadIdx.x < 32) {
        int j = threadIdx.x;
        float cz = Lzb[j], ch = Lhb[j];
        #pragma unroll 8
        for (int k = 0; k < 32; k++) {
            cz += bz[k] * LzW[k * 32 + j];
            ch += bh[k] * LhW[k * 32 + j];
        }
        g_cz[j] = cz; g_ch[j] = ch;
        #pragma unroll
        for (int f = 0; f < 4; f++) {
            float mz = 0.f, mh = 0.f;
            #pragma unroll 8
            for (int k = 0; k < 32; k++) {
                mz += Wz[f * 32 + k] * LzW[k * 32 + j];
                mh += Wh[f * 32 + k] * LhW[k * 32 + j];
            }
            g_Mz[f * 32 + j] = mz;
            g_Mh[f * 32 + j] = mh;
        }
        if (j == 0) {
            float m = att[0];
            for (int p = 1; p < PER; p++) m = fmaxf(m, att[p]);
            float s = 0.f, e[PER];
            for (int p = 0; p < PER; p++) { e[p] = expf(att[p] - m); s += e[p]; }
            for (int p = 0; p < PER; p++) g_probs[p] = e[p] / s;
        }
    }

    int t = blockIdx.x * blockDim.x + threadIdx.x;
    if (t >= N_EDGES / 4) return;
    int4 s = src4[t];
    int4 d = dst4[t];
    int p0 = atomicAdd(&g_cnt[d.x], 1); if (p0 < CAP) g_esrc[d.x * CAP + p0] = s.x;
    int p1 = atomicAdd(&g_cnt[d.y], 1); if (p1 < CAP) g_esrc[d.y * CAP + p1] = s.y;
    int p2 = atomicAdd(&g_cnt[d.z], 1); if (p2 < CAP) g_esrc[d.z * CAP + p2] = s.z;
    int p3 = atomicAdd(&g_cnt[d.w], 1); if (p3 < CAP) g_esrc[d.w * CAP + p3] = s.w;
}

// ------------------------------------------------------------------
// Pre-scale: g_Xs[n] = (deg[n]+1)^{-1/2} * x[n].  8 threads per node.
__global__ void k_scale(const float* __restrict__ x) {
    int i = blockIdx.x * blockDim.x + threadIdx.x;
    int n = i >> 3;
    int q = i & 7;
    if (n >= N_NODES) return;
    float dn = rsqrtf((float)g_cnt[n] + 1.0f);
    float4 v = reinterpret_cast<const float4*>(x)[n * 8 + q];
    v.x *= dn; v.y *= dn; v.z *= dn; v.w *= dn;
    reinterpret_cast<float4*>(g_Xs)[n * 8 + q] = v;
}

// ------------------------------------------------------------------
// Fused gather + GRU + attention + output.  8 lanes per node.
// __launch_bounds__(256, 4): cap at 64 regs -> 4 blocks/SM (was 3 @72 regs).
__global__ void __launch_bounds__(256, 4)
k_fused(const float* __restrict__ outW, const float* __restrict__ outb,
        float* __restrict__ out) {
    __shared__ float sMz[128], sMh[128], scz[32], sch[32], sp[PER], sOW[256], sOb[PER];
    int t = threadIdx.x;   // block 256
    if (t < 128) { sMz[t] = g_Mz[t]; sMh[t] = g_Mh[t]; }
    if (t < 32)  { scz[t] = g_cz[t]; sch[t] = g_ch[t]; }
    if (t < PER) { sp[t] = g_probs[t]; sOb[t] = outb[t]; }
    sOW[t] = outW[t];
    __syncthreads();

    int gi = blockIdx.x * blockDim.x + t;
    int n_raw = gi >> 3;
    bool live = (n_raw < N_NODES);
    int n = live ? n_raw : (N_NODES - 1);        // clamp: keep warp uniform for shfl
    int w = t & 31;                              // lane in warp
    int q = w & 7;                               // lane in 8-group
    int gbase = w & ~7;                          // group base lane

    // ---- gather: lane q owns float4 chunk q of the 32-float row ----
    int cnt = g_cnt[n];
    int deg = cnt > CAP ? CAP : cnt;
    const int* row = &g_esrc[n * CAP];
    const float4* xs4 = reinterpret_cast<const float4*>(g_Xs);

    float4 acc = xs4[n * 8 + q];                 // self-loop term (pre-scaled)
    int e = 0;
    for (; e + 4 <= deg; e += 4) {
        int4 s4 = *reinterpret_cast<const int4*>(row + e);   // 16B-aligned (CAP=64)
        float4 v0 = xs4[s4.x * 8 + q];
        float4 v1 = xs4[s4.y * 8 + q];
        float4 v2 = xs4[s4.z * 8 + q];
        float4 v3 = xs4[s4.w * 8 + q];
        acc.x += (v0.x + v1.x) + (v2.x + v3.x);
        acc.y += (v0.y + v1.y) + (v2.y + v3.y);
        acc.z += (v0.z + v1.z) + (v2.z + v3.z);
        acc.w += (v0.w + v1.w) + (v2.w + v3.w);
    }
    for (; e < deg; e++) {
        int s = row[e];
        float4 v = xs4[s * 8 + q];
        acc.x += v.x; acc.y += v.y; acc.z += v.z; acc.w += v.w;
    }
    // reset counter for the next graph replay (only the owner group reads cnt[n]
    // in this kernel; k_scale, the only other reader, has already completed)
    if (live && q == 0) g_cnt[n] = 0;

    float dn = rsqrtf((float)cnt + 1.0f);
    acc.x *= dn; acc.y *= dn; acc.z *= dn; acc.w *= dn;
    // acc = yf[4q .. 4q+3] of row layout [f=0..3][p=0..7]

    // ---- preload this lane's 4 hidden-channel weight columns ----
    int j0 = q * 4;
    float rMz[4][4], rMh[4][4], rcz[4], rch[4];
    #pragma unroll
    for (int i = 0; i < 4; i++) {
        rcz[i] = scz[j0 + i];
        rch[i] = sch[j0 + i];
        #pragma unroll
        for (int f = 0; f < 4; f++) {
            rMz[f][i] = sMz[f * 32 + j0 + i];
            rMh[f][i] = sMh[f * 32 + j0 + i];
        }
    }

    float Hacc[4] = {0.f, 0.f, 0.f, 0.f};
    #pragma unroll
    for (int p = 0; p < PER; p++) {
        float csel = (p & 3) == 0 ? acc.x : (p & 3) == 1 ? acc.y : (p & 3) == 2 ? acc.z : acc.w;
        int off = p >> 2;
        float y0 = __shfl_sync(0xffffffffu, csel, gbase + 0 + off);
        float y1 = __shfl_sync(0xffffffffu, csel, gbase + 2 + off);
        float y2 = __shfl_sync(0xffffffffu, csel, gbase + 4 + off);
        float y3 = __shfl_sync(0xffffffffu, csel, gbase + 6 + off);
        float pw = sp[p];
        #pragma unroll
        for (int i = 0; i < 4; i++) {
            float az = rcz[i] + y0 * rMz[0][i] + y1 * rMz[1][i] + y2 * rMz[2][i] + y3 * rMz[3][i];
            float ah = rch[i] + y0 * rMh[0][i] + y1 * rMh[1][i] + y2 * rMh[2][i] + y3 * rMh[3][i];
            // sigmoid(-az)*tanh(ah) = (e^{2ah}-1) / ((1+e^{az})(e^{2ah}+1))
            float ea = __expf(az);
            float e2 = __expf(2.0f * fminf(ah, 15.0f));
            float val = __fdividef(e2 - 1.0f, (1.0f + ea) * (e2 + 1.0f));
            Hacc[i] += pw * val;
        }
    }

    // ---- output: partial o[8] over this lane's 4 channels, then 8-lane butterfly ----
    float o[PER];
    #pragma unroll
    for (int k = 0; k < PER; k++) o[k] = sOb[k] * 0.125f;   // split bias so 8-lane sum = bias
    #pragma unroll
    for (int i = 0; i < 4; i++) {
        float r = fmaxf(Hacc[i], 0.0f);
        #pragma unroll
        for (int k = 0; k < PER; k++) o[k] += r * sOW[(j0 + i) * 8 + k];
    }
    #pragma unroll
    for (int m = 1; m <= 4; m <<= 1) {
        #pragma unroll
        for (int k = 0; k < PER; k++)
            o[k] += __shfl_xor_sync(0xffffffffu, o[k], m);
    }
    float val = (q & 4) ? ((q & 2) ? ((q & 1) ? o[7] : o[6]) : ((q & 1) ? o[5] : o[4]))
                        : ((q & 2) ? ((q & 1) ? o[3] : o[2]) : ((q & 1) ? o[1] : o[0]));
    if (live) out[n * 8 + q] = val;
}

// ------------------------------------------------------------------
extern "C" void kernel_launch(void* const* d_in, const int* in_sizes, int n_in,
                              void* d_out, int out_size) {
    const float* x   = (const float*)d_in[0];
    const int* ei    = (const int*)d_in[1];
    const float* Wz  = (const float*)d_in[2];
    const float* bz  = (const float*)d_in[3];
    const float* Wh  = (const float*)d_in[6];
    const float* bh  = (const float*)d_in[7];
    const float* LzW = (const float*)d_in[8];
    const float* Lzb = (const float*)d_in[9];
    const float* LhW = (const float*)d_in[12];
    const float* Lhb = (const float*)d_in[13];
    const float* att = (const float*)d_in[14];
    const float* outW = (const float*)d_in[15];
    const float* outb = (const float*)d_in[16];
    float* out = (float*)d_out;

    const int4* src4 = (const int4*)ei;                    // edge_index[0,:]
    const int4* dst4 = (const int4*)(ei + N_EDGES);        // edge_index[1,:]

    k_fill<<<(N_EDGES / 4 + 255) / 256, 256>>>(src4, dst4, Wz, bz, Wh, bh,
                                               LzW, Lzb, LhW, Lhb, att);
    k_scale<<<(N_NODES * 8 + 255) / 256, 256>>>(x);
    k_fused<<<(N_NODES * 8 + 255) / 256, 256>>>(outW, outb, out);
}

// round 11
// speedup vs baseline: 1.1864x; 1.0072x over previous
#include <cuda_runtime.h>
#include <math.h>

#define N_NODES 50000
#define N_EDGES 800000
#define PER 8
#define CAP 64   // max in-degree slots; deg ~ Poisson(16), P(>=64) ~ 0

// ---- device scratch (static allocations only; zero-initialized at load) ----
__device__ int   g_cnt[N_NODES];                        // in-degree counter (self-resetting)
__device__ __align__(16) int g_esrc[N_NODES * CAP];     // binned src indices per dst
__device__ __align__(16) float g_Xs[N_NODES * 32];      // dinv[n] * x[n]  [N,4,8]
__device__ float g_Mz[128];                             // 0.5 * Wz @ LzW[:32]  -> [4][32]
__device__ float g_Mh[128];                             // Wh @ LhW[:32]        -> [4][32]
__device__ float g_cz[32];                              // 0.5 * (bz @ LzW[:32] + Lzb)
__device__ float g_ch[32];                              // bh @ LhW[:32] + Lhb
__device__ float g_probs[PER];                          // 0.5 * softmax(att)

__device__ __forceinline__ float tanh_fast(float v) {
    float r; asm("tanh.approx.f32 %0, %1;" : "=f"(r) : "f"(v)); return r;
}

// ------------------------------------------------------------------
// Bin edges by destination (4 edges/thread, int4). Block 0 lanes 0-31 also
// fold the gate weights (with the 0.5 factors for the tanh-identity GRU).
__global__ void k_fill(const int4* __restrict__ src4, const int4* __restrict__ dst4,
                       const float* __restrict__ Wz, const float* __restrict__ bz,
                       const float* __restrict__ Wh, const float* __restrict__ bh,
                       const float* __restrict__ LzW, const float* __restrict__ Lzb,
                       const float* __restrict__ LhW, const float* __restrict__ Lhb,
                       const float* __restrict__ att) {
    if (blockIdx.x == 0 && threadIdx.x < 32) {
        int j = threadIdx.x;
        float cz = Lzb[j], ch = Lhb[j];
        #pragma unroll 8
        for (int k = 0; k < 32; k++) {
            cz += bz[k] * LzW[k * 32 + j];
            ch += bh[k] * LhW[k * 32 + j];
        }
        g_cz[j] = 0.5f * cz;           // az/2 folded into constants
        g_ch[j] = ch;
        #pragma unroll
        for (int f = 0; f < 4; f++) {
            float mz = 0.f, mh = 0.f;
            #pragma unroll 8
            for (int k = 0; k < 32; k++) {
                mz += Wz[f * 32 + k] * LzW[k * 32 + j];
                mh += Wh[f * 32 + k] * LhW[k * 32 + j];
            }
            g_Mz[f * 32 + j] = 0.5f * mz;
            g_Mh[f * 32 + j] = mh;
        }
        if (j == 0) {
            float m = att[0];
            for (int p = 1; p < PER; p++) m = fmaxf(m, att[p]);
            float s = 0.f, e[PER];
            for (int p = 0; p < PER; p++) { e[p] = expf(att[p] - m); s += e[p]; }
            for (int p = 0; p < PER; p++) g_probs[p] = 0.5f * e[p] / s;  // 0.5 from sigmoid identity
        }
    }

    int t = blockIdx.x * blockDim.x + threadIdx.x;
    if (t >= N_EDGES / 4) return;
    int4 s = src4[t];
    int4 d = dst4[t];
    int p0 = atomicAdd(&g_cnt[d.x], 1); if (p0 < CAP) g_esrc[d.x * CAP + p0] = s.x;
    int p1 = atomicAdd(&g_cnt[d.y], 1); if (p1 < CAP) g_esrc[d.y * CAP + p1] = s.y;
    int p2 = atomicAdd(&g_cnt[d.z], 1); if (p2 < CAP) g_esrc[d.z * CAP + p2] = s.z;
    int p3 = atomicAdd(&g_cnt[d.w], 1); if (p3 < CAP) g_esrc[d.w * CAP + p3] = s.w;
}

// ------------------------------------------------------------------
// Pre-scale: g_Xs[n] = (deg[n]+1)^{-1/2} * x[n].  8 threads per node.
__global__ void k_scale(const float* __restrict__ x) {
    int i = blockIdx.x * blockDim.x + threadIdx.x;
    int n = i >> 3;
    int q = i & 7;
    if (n >= N_NODES) return;
    float dn = rsqrtf((float)g_cnt[n] + 1.0f);
    float4 v = reinterpret_cast<const float4*>(x)[n * 8 + q];
    v.x *= dn; v.y *= dn; v.z *= dn; v.w *= dn;
    reinterpret_cast<float4*>(g_Xs)[n * 8 + q] = v;
}

// ------------------------------------------------------------------
// Fused gather + GRU + attention + output.  8 lanes per node.
__global__ void __launch_bounds__(256, 4)
k_fused(const float* __restrict__ outW, const float* __restrict__ outb,
        float* __restrict__ out) {
    __shared__ float sMz[128], sMh[128], scz[32], sch[32], sp[PER], sOW[256], sOb[PER];
    int t = threadIdx.x;   // block 256
    if (t < 128) { sMz[t] = g_Mz[t]; sMh[t] = g_Mh[t]; }
    if (t < 32)  { scz[t] = g_cz[t]; sch[t] = g_ch[t]; }
    if (t < PER) { sp[t] = g_probs[t]; sOb[t] = outb[t]; }
    sOW[t] = outW[t];
    __syncthreads();

    int gi = blockIdx.x * blockDim.x + t;
    int n_raw = gi >> 3;
    bool live = (n_raw < N_NODES);
    int n = live ? n_raw : (N_NODES - 1);        // clamp: keep warp uniform for shfl
    int w = t & 31;                              // lane in warp
    int q = w & 7;                               // lane in 8-group
    int gbase = w & ~7;                          // group base lane

    // ---- gather: lane q owns float4 chunk q of the 32-float row ----
    int cnt = g_cnt[n];
    int deg = cnt > CAP ? CAP : cnt;
    const int* row = &g_esrc[n * CAP];
    const float4* xs4 = reinterpret_cast<const float4*>(g_Xs);

    float4 acc = xs4[n * 8 + q];                 // self-loop term (pre-scaled)
    int e = 0;
    for (; e + 4 <= deg; e += 4) {
        int4 s4 = *reinterpret_cast<const int4*>(row + e);   // 16B-aligned (CAP=64)
        float4 v0 = xs4[s4.x * 8 + q];
        float4 v1 = xs4[s4.y * 8 + q];
        float4 v2 = xs4[s4.z * 8 + q];
        float4 v3 = xs4[s4.w * 8 + q];
        acc.x += (v0.x + v1.x) + (v2.x + v3.x);
        acc.y += (v0.y + v1.y) + (v2.y + v3.y);
        acc.z += (v0.z + v1.z) + (v2.z + v3.z);
        acc.w += (v0.w + v1.w) + (v2.w + v3.w);
    }
    for (; e < deg; e++) {
        int s = row[e];
        float4 v = xs4[s * 8 + q];
        acc.x += v.x; acc.y += v.y; acc.z += v.z; acc.w += v.w;
    }
    // reset counter for the next graph replay (only the owner group reads cnt[n]
    // in this kernel; k_scale, the only other reader, has already completed)
    if (live && q == 0) g_cnt[n] = 0;

    float dn = rsqrtf((float)cnt + 1.0f);
    acc.x *= dn; acc.y *= dn; acc.z *= dn; acc.w *= dn;
    // acc = yf[4q .. 4q+3] of row layout [f=0..3][p=0..7]

    // ---- preload this lane's 4 hidden-channel weight columns ----
    int j0 = q * 4;
    float rMz[4][4], rMh[4][4], rcz[4], rch[4];
    #pragma unroll
    for (int i = 0; i < 4; i++) {
        rcz[i] = scz[j0 + i];
        rch[i] = sch[j0 + i];
        #pragma unroll
        for (int f = 0; f < 4; f++) {
            rMz[f][i] = sMz[f * 32 + j0 + i];
            rMh[f][i] = sMh[f * 32 + j0 + i];
        }
    }

    float Hacc[4] = {0.f, 0.f, 0.f, 0.f};
    #pragma unroll
    for (int p = 0; p < PER; p++) {
        float csel = (p & 3) == 0 ? acc.x : (p & 3) == 1 ? acc.y : (p & 3) == 2 ? acc.z : acc.w;
        int off = p >> 2;
        float y0 = __shfl_sync(0xffffffffu, csel, gbase + 0 + off);
        float y1 = __shfl_sync(0xffffffffu, csel, gbase + 2 + off);
        float y2 = __shfl_sync(0xffffffffu, csel, gbase + 4 + off);
        float y3 = __shfl_sync(0xffffffffu, csel, gbase + 6 + off);
        float pw = sp[p];   // = softmax(att)[p] / 2
        #pragma unroll
        for (int i = 0; i < 4; i++) {
            // azh = az/2 (0.5 folded into rMz/rcz); ah unscaled
            float azh = rcz[i] + y0 * rMz[0][i] + y1 * rMz[1][i] + y2 * rMz[2][i] + y3 * rMz[3][i];
            float ah  = rch[i] + y0 * rMh[0][i] + y1 * rMh[1][i] + y2 * rMh[2][i] + y3 * rMh[3][i];
            // sigmoid(-az)*tanh(ah) = 0.5*(1 - tanh(az/2))*tanh(ah); 0.5 folded into pw
            float t1 = tanh_fast(azh);
            float t2 = tanh_fast(ah);
            Hacc[i] += pw * (t2 - t1 * t2);
        }
    }

    // ---- output: partial o[8] over this lane's 4 channels, then 8-lane butterfly ----
    float o[PER];
    #pragma unroll
    for (int k = 0; k < PER; k++) o[k] = sOb[k] * 0.125f;   // split bias so 8-lane sum = bias
    #pragma unroll
    for (int i = 0; i < 4; i++) {
        float r = fmaxf(Hacc[i], 0.0f);
        #pragma unroll
        for (int k = 0; k < PER; k++) o[k] += r * sOW[(j0 + i) * 8 + k];
    }
    #pragma unroll
    for (int m = 1; m <= 4; m <<= 1) {
        #pragma unroll
        for (int k = 0; k < PER; k++)
            o[k] += __shfl_xor_sync(0xffffffffu, o[k], m);
    }
    float val = (q & 4) ? ((q & 2) ? ((q & 1) ? o[7] : o[6]) : ((q & 1) ? o[5] : o[4]))
                        : ((q & 2) ? ((q & 1) ? o[3] : o[2]) : ((q & 1) ? o[1] : o[0]));
    if (live) out[n * 8 + q] = val;
}

// ------------------------------------------------------------------
extern "C" void kernel_launch(void* const* d_in, const int* in_sizes, int n_in,
                              void* d_out, int out_size) {
    const float* x   = (const float*)d_in[0];
    const int* ei    = (const int*)d_in[1];
    const float* Wz  = (const float*)d_in[2];
    const float* bz  = (const float*)d_in[3];
    const float* Wh  = (const float*)d_in[6];
    const float* bh  = (const float*)d_in[7];
    const float* LzW = (const float*)d_in[8];
    const float* Lzb = (const float*)d_in[9];
    const float* LhW = (const float*)d_in[12];
    const float* Lhb = (const float*)d_in[13];
    const float* att = (const float*)d_in[14];
    const float* outW = (const float*)d_in[15];
    const float* outb = (const float*)d_in[16];
    float* out = (float*)d_out;

    const int4* src4 = (const int4*)ei;                    // edge_index[0,:]
    const int4* dst4 = (const int4*)(ei + N_EDGES);        // edge_index[1,:]

    k_fill<<<(N_EDGES / 4 + 255) / 256, 256>>>(src4, dst4, Wz, bz, Wh, bh,
                                               LzW, Lzb, LhW, Lhb, att);
    k_scale<<<(N_NODES * 8 + 255) / 256, 256>>>(x);
    k_fused<<<(N_NODES * 8 + 255) / 256, 256>>>(outW, outb, out);
}

// round 13
// speedup vs baseline: 1.2739x; 1.0738x over previous
#include <cuda_runtime.h>
#include <math.h>

#define N_NODES 50000
#define N_EDGES 800000
#define PER 8
#define CAP 64   // max in-degree slots; deg ~ Poisson(16), P(>=64) ~ 0

// ---- device scratch (static allocations only; zero-initialized at load) ----
__device__ int   g_cnt[N_NODES];                        // in-degree counter (self-resetting)
__device__ __align__(16) int g_esrc[N_NODES * CAP];     // binned src indices per dst
__device__ __align__(16) float g_Xs[N_NODES * 32];      // dinv[n] * x[n]  [N,4,8]
__device__ float g_Mz[128];                             // 0.5 * Wz @ LzW[:32]  -> [4][32]
__device__ float g_Mh[128];                             // Wh @ LhW[:32]        -> [4][32]
__device__ float g_cz[32];                              // 0.5 * (bz @ LzW[:32] + Lzb)
__device__ float g_ch[32];                              // bh @ LhW[:32] + Lhb
__device__ float g_probs[PER];                          // 0.5 * softmax(att)

__device__ __forceinline__ float tanh_fast(float v) {
    float r; asm("tanh.approx.f32 %0, %1;" : "=f"(r) : "f"(v)); return r;
}

// ------------------------------------------------------------------
// Bin edges by destination: one edge per thread (best-measured variant).
// Block 0 lanes 0-31 also fold the gate weights (with 0.5 factors for the
// tanh-identity GRU).
__global__ void k_fill(const int* __restrict__ src, const int* __restrict__ dst,
                       const float* __restrict__ Wz, const float* __restrict__ bz,
                       const float* __restrict__ Wh, const float* __restrict__ bh,
                       const float* __restrict__ LzW, const float* __restrict__ Lzb,
                       const float* __restrict__ LhW, const float* __restrict__ Lhb,
                       const float* __restrict__ att) {
    if (blockIdx.x == 0 && threadIdx.x < 32) {
        int j = threadIdx.x;
        float cz = Lzb[j], ch = Lhb[j];
        #pragma unroll 8
        for (int k = 0; k < 32; k++) {
            cz += bz[k] * LzW[k * 32 + j];
            ch += bh[k] * LhW[k * 32 + j];
        }
        g_cz[j] = 0.5f * cz;           // az/2 folded into constants
        g_ch[j] = ch;
        #pragma unroll
        for (int f = 0; f < 4; f++) {
            float mz = 0.f, mh = 0.f;
            #pragma unroll 8
            for (int k = 0; k < 32; k++) {
                mz += Wz[f * 32 + k] * LzW[k * 32 + j];
                mh += Wh[f * 32 + k] * LhW[k * 32 + j];
            }
            g_Mz[f * 32 + j] = 0.5f * mz;
            g_Mh[f * 32 + j] = mh;
        }
        if (j == 0) {
            float m = att[0];
            for (int p = 1; p < PER; p++) m = fmaxf(m, att[p]);
            float s = 0.f, e[PER];
            for (int p = 0; p < PER; p++) { e[p] = expf(att[p] - m); s += e[p]; }
            for (int p = 0; p < PER; p++) g_probs[p] = 0.5f * e[p] / s;  // 0.5 from sigmoid identity
        }
    }

    int e = blockIdx.x * blockDim.x + threadIdx.x;
    if (e >= N_EDGES) return;
    int s = __ldg(&src[e]);
    int d = __ldg(&dst[e]);
    int pos = atomicAdd(&g_cnt[d], 1);
    if (pos < CAP) g_esrc[d * CAP + pos] = s;
}

// ------------------------------------------------------------------
// Pre-scale: g_Xs[n] = (deg[n]+1)^{-1/2} * x[n].  8 threads per node.
__global__ void k_scale(const float* __restrict__ x) {
    int i = blockIdx.x * blockDim.x + threadIdx.x;
    int n = i >> 3;
    int q = i & 7;
    if (n >= N_NODES) return;
    float dn = rsqrtf((float)g_cnt[n] + 1.0f);
    float4 v = reinterpret_cast<const float4*>(x)[n * 8 + q];
    v.x *= dn; v.y *= dn; v.z *= dn; v.w *= dn;
    reinterpret_cast<float4*>(g_Xs)[n * 8 + q] = v;
}

// ------------------------------------------------------------------
// Fused gather + GRU + attention + output.  8 lanes per node.
// Gather loop is software-pipelined: quad i+1's index vector is loaded
// before quad i's four gathers are issued (halves the exposed chain).
__global__ void __launch_bounds__(256, 4)
k_fused(const float* __restrict__ outW, const float* __restrict__ outb,
        float* __restrict__ out) {
    __shared__ float sMz[128], sMh[128], scz[32], sch[32], sp[PER], sOW[256], sOb[PER];
    int t = threadIdx.x;   // block 256
    if (t < 128) { sMz[t] = g_Mz[t]; sMh[t] = g_Mh[t]; }
    if (t < 32)  { scz[t] = g_cz[t]; sch[t] = g_ch[t]; }
    if (t < PER) { sp[t] = g_probs[t]; sOb[t] = outb[t]; }
    sOW[t] = outW[t];
    __syncthreads();

    int gi = blockIdx.x * blockDim.x + t;
    int n_raw = gi >> 3;
    bool live = (n_raw < N_NODES);
    int n = live ? n_raw : (N_NODES - 1);        // clamp: keep warp uniform for shfl
    int w = t & 31;                              // lane in warp
    int q = w & 7;                               // lane in 8-group
    int gbase = w & ~7;                          // group base lane

    // ---- gather: lane q owns float4 chunk q of the 32-float row ----
    int cnt = g_cnt[n];
    int deg = cnt > CAP ? CAP : cnt;
    const int* row = &g_esrc[n * CAP];
    const float4* xs4 = reinterpret_cast<const float4*>(g_Xs);

    float4 acc = xs4[n * 8 + q];                 // self-loop term (pre-scaled)
    int nq = deg >> 2;                           // full quads
    if (nq > 0) {
        int4 s4 = *reinterpret_cast<const int4*>(row);       // 16B-aligned (CAP=64)
        for (int i = 1; i < nq; i++) {
            int4 nxt = *reinterpret_cast<const int4*>(row + i * 4);  // prefetch next quad
            float4 v0 = xs4[s4.x * 8 + q];
            float4 v1 = xs4[s4.y * 8 + q];
            float4 v2 = xs4[s4.z * 8 + q];
            float4 v3 = xs4[s4.w * 8 + q];
            acc.x += (v0.x + v1.x) + (v2.x + v3.x);
            acc.y += (v0.y + v1.y) + (v2.y + v3.y);
            acc.z += (v0.z + v1.z) + (v2.z + v3.z);
            acc.w += (v0.w + v1.w) + (v2.w + v3.w);
            s4 = nxt;
        }
        float4 v0 = xs4[s4.x * 8 + q];
        float4 v1 = xs4[s4.y * 8 + q];
        float4 v2 = xs4[s4.z * 8 + q];
        float4 v3 = xs4[s4.w * 8 + q];
        acc.x += (v0.x + v1.x) + (v2.x + v3.x);
        acc.y += (v0.y + v1.y) + (v2.y + v3.y);
        acc.z += (v0.z + v1.z) + (v2.z + v3.z);
        acc.w += (v0.w + v1.w) + (v2.w + v3.w);
    }
    for (int e = nq << 2; e < deg; e++) {
        int s = row[e];
        float4 v = xs4[s * 8 + q];
        acc.x += v.x; acc.y += v.y; acc.z += v.z; acc.w += v.w;
    }
    // reset counter for the next graph replay (only the owner group reads cnt[n]
    // in this kernel; k_scale, the only other reader, has already completed)
    if (live && q == 0) g_cnt[n] = 0;

    float dn = rsqrtf((float)cnt + 1.0f);
    acc.x *= dn; acc.y *= dn; acc.z *= dn; acc.w *= dn;
    // acc = yf[4q .. 4q+3] of row layout [f=0..3][p=0..7]

    // ---- preload this lane's 4 hidden-channel weight columns ----
    int j0 = q * 4;
    float rMz[4][4], rMh[4][4], rcz[4], rch[4];
    #pragma unroll
    for (int i = 0; i < 4; i++) {
        rcz[i] = scz[j0 + i];
        rch[i] = sch[j0 + i];
        #pragma unroll
        for (int f = 0; f < 4; f++) {
            rMz[f][i] = sMz[f * 32 + j0 + i];
            rMh[f][i] = sMh[f * 32 + j0 + i];
        }
    }

    float Hacc[4] = {0.f, 0.f, 0.f, 0.f};
    #pragma unroll
    for (int p = 0; p < PER; p++) {
        float csel = (p & 3) == 0 ? acc.x : (p & 3) == 1 ? acc.y : (p & 3) == 2 ? acc.z : acc.w;
        int off = p >> 2;
        float y0 = __shfl_sync(0xffffffffu, csel, gbase + 0 + off);
        float y1 = __shfl_sync(0xffffffffu, csel, gbase + 2 + off);
        float y2 = __shfl_sync(0xffffffffu, csel, gbase + 4 + off);
        float y3 = __shfl_sync(0xffffffffu, csel, gbase + 6 + off);
        float pw = sp[p];   // = softmax(att)[p] / 2
        #pragma unroll
        for (int i = 0; i < 4; i++) {
            // azh = az/2 (0.5 folded into rMz/rcz); ah unscaled
            float azh = rcz[i] + y0 * rMz[0][i] + y1 * rMz[1][i] + y2 * rMz[2][i] + y3 * rMz[3][i];
            float ah  = rch[i] + y0 * rMh[0][i] + y1 * rMh[1][i] + y2 * rMh[2][i] + y3 * rMh[3][i];
            // sigmoid(-az)*tanh(ah) = 0.5*(1 - tanh(az/2))*tanh(ah); 0.5 folded into pw
            float t1 = tanh_fast(azh);
            float t2 = tanh_fast(ah);
            Hacc[i] += pw * (t2 - t1 * t2);
        }
    }

    // ---- output: partial o[8] over this lane's 4 channels, then 8-lane butterfly ----
    float o[PER];
    #pragma unroll
    for (int k = 0; k < PER; k++) o[k] = sOb[k] * 0.125f;   // split bias so 8-lane sum = bias
    #pragma unroll
    for (int i = 0; i < 4; i++) {
        float r = fmaxf(Hacc[i], 0.0f);
        #pragma unroll
        for (int k = 0; k < PER; k++) o[k] += r * sOW[(j0 + i) * 8 + k];
    }
    #pragma unroll
    for (int m = 1; m <= 4; m <<= 1) {
        #pragma unroll
        for (int k = 0; k < PER; k++)
            o[k] += __shfl_xor_sync(0xffffffffu, o[k], m);
    }
    float val = (q & 4) ? ((q & 2) ? ((q & 1) ? o[7] : o[6]) : ((q & 1) ? o[5] : o[4]))
                        : ((q & 2) ? ((q & 1) ? o[3] : o[2]) : ((q & 1) ? o[1] : o[0]));
    if (live) out[n * 8 + q] = val;
}

// ------------------------------------------------------------------
extern "C" void kernel_launch(void* const* d_in, const int* in_sizes, int n_in,
                              void* d_out, int out_size) {
    const float* x   = (const float*)d_in[0];
    const int* ei    = (const int*)d_in[1];
    const float* Wz  = (const float*)d_in[2];
    const float* bz  = (const float*)d_in[3];
    const float* Wh  = (const float*)d_in[6];
    const float* bh  = (const float*)d_in[7];
    const float* LzW = (const float*)d_in[8];
    const float* Lzb = (const float*)d_in[9];
    const float* LhW = (const float*)d_in[12];
    const float* Lhb = (const float*)d_in[13];
    const float* att = (const float*)d_in[14];
    const float* outW = (const float*)d_in[15];
    const float* outb = (const float*)d_in[16];
    float* out = (float*)d_out;

    const int* src = ei;             // edge_index[0,:]
    const int* dst = ei + N_EDGES;   // edge_index[1,:]

    k_fill<<<(N_EDGES + 255) / 256, 256>>>(src, dst, Wz, bz, Wh, bh,
                                           LzW, Lzb, LhW, Lhb, att);
    k_scale<<<(N_NODES * 8 + 255) / 256, 256>>>(x);
    k_fused<<<(N_NODES * 8 + 255) / 256, 256>>>(outW, outb, out);
}